// round 8
// baseline (speedup 1.0000x reference)
#include <cuda_runtime.h>
#include <cuda_fp16.h>
#include <stdint.h>

#define N_NODES 1000000
#define F 16
#define MAX_E 4000000
#define SCAN_B 1024

// Scratch (allocation-free rule: __device__ globals)
__device__ __half g_hs[(size_t)N_NODES * F];  // h*dinv[src], fp16 (32MB)
__device__ float  g_dinv[N_NODES];            // rsqrt(deg+1)
__device__ int    g_cnt[N_NODES];             // histogram -> downward cursors
__device__ int2   g_seg[N_NODES];             // (begin, end) of dst segment
__device__ int    g_total;                    // running base for block offsets
__device__ int    g_src[MAX_E];               // src ids grouped by dst

// ---------------------------------------------------------------------------
// K0: zero histogram (+ global base counter)
// ---------------------------------------------------------------------------
__global__ void k_zero(int n4) {
    int i = blockIdx.x * blockDim.x + threadIdx.x;
    if (i < n4) reinterpret_cast<int4*>(g_cnt)[i] = make_int4(0, 0, 0, 0);
    if (i == 0) g_total = 0;
}

// ---------------------------------------------------------------------------
// K1: histogram of dst (= degree without self loop)
// ---------------------------------------------------------------------------
__global__ void k_hist(const int* __restrict__ col, int E, int n) {
    int e = blockIdx.x * blockDim.x + threadIdx.x;
    if (e < E) {
        int c = col[e];
        if ((unsigned)c < (unsigned)n) atomicAdd(&g_cnt[c], 1);
    }
}

// ---------------------------------------------------------------------------
// K2: single-kernel exclusive scan (warp shuffles; block base via atomicAdd
// on g_total -- segment layout is schedule-dependent but the per-node sum is
// order-free). Writes g_seg=(begin,end), cursor g_cnt[i]=end, and dinv.
// ---------------------------------------------------------------------------
__global__ void __launch_bounds__(SCAN_B)
k_scan(int n) {
    __shared__ int wsum[32];
    __shared__ int sbase;

    int i    = blockIdx.x * SCAN_B + threadIdx.x;
    int lane = threadIdx.x & 31;
    int wid  = threadIdx.x >> 5;

    int v = (i < n) ? g_cnt[i] : 0;

    int x = v;
#pragma unroll
    for (int d = 1; d < 32; d <<= 1) {
        int t = __shfl_up_sync(0xffffffffu, x, d);
        if (lane >= d) x += t;
    }
    if (lane == 31) wsum[wid] = x;
    __syncthreads();

    if (wid == 0) {
        int w = wsum[lane];
#pragma unroll
        for (int d = 1; d < 32; d <<= 1) {
            int t = __shfl_up_sync(0xffffffffu, w, d);
            if (lane >= d) w += t;
        }
        wsum[lane] = w;
        if (lane == 31) sbase = atomicAdd(&g_total, w);
    }
    __syncthreads();

    if (i < n) {
        int excl = x - v + (wid ? wsum[wid - 1] : 0) + sbase;
        g_seg[i]  = make_int2(excl, excl + v);
        g_cnt[i]  = excl + v;          // downward cursor = segment end
        g_dinv[i] = rsqrtf((float)v + 1.0f);
    }
}

// ---------------------------------------------------------------------------
// K3: h_scaled = (x @ W) * dinv -> fp16. Pure streaming.
// ---------------------------------------------------------------------------
__global__ void __launch_bounds__(256)
k_h(const float4* __restrict__ x4, const float* __restrict__ W, int n) {
    __shared__ float sW[F * F];
    sW[threadIdx.x] = W[threadIdx.x];    // blockDim == 256 == F*F
    __syncthreads();

    int i = blockIdx.x * 256 + threadIdx.x;
    if (i >= n) return;

    float4 xv0 = x4[(size_t)i * 4 + 0];
    float4 xv1 = x4[(size_t)i * 4 + 1];
    float4 xv2 = x4[(size_t)i * 4 + 2];
    float4 xv3 = x4[(size_t)i * 4 + 3];
    float xr[F] = {xv0.x, xv0.y, xv0.z, xv0.w,
                   xv1.x, xv1.y, xv1.z, xv1.w,
                   xv2.x, xv2.y, xv2.z, xv2.w,
                   xv3.x, xv3.y, xv3.z, xv3.w};

    float acc[F];
#pragma unroll
    for (int j = 0; j < F; j++) acc[j] = 0.0f;
#pragma unroll
    for (int k = 0; k < F; k++) {
        float xk = xr[k];
#pragma unroll
        for (int j = 0; j < F; j++) acc[j] = fmaf(xk, sW[k * F + j], acc[j]);
    }

    float di = g_dinv[i];

    uint4 hpk[2];
    __half2* hh = reinterpret_cast<__half2*>(&hpk[0]);
#pragma unroll
    for (int q = 0; q < 8; q++)
        hh[q] = __floats2half2_rn(acc[2 * q] * di, acc[2 * q + 1] * di);
    uint4* hp = reinterpret_cast<uint4*>(g_hs + (size_t)i * F);
    hp[0] = hpk[0];
    hp[1] = hpk[1];
}

// ---------------------------------------------------------------------------
// K4: scatter src ids. Cursor decrement yields the ABSOLUTE slot directly
// (no g_seg lookup). Lean kernel -> full occupancy, max outstanding atomics.
// ---------------------------------------------------------------------------
__global__ void k_scatter(const int* __restrict__ ei, int E, int n) {
    int e = blockIdx.x * blockDim.x + threadIdx.x;
    if (e >= E) return;
    int r = ei[e];
    int c = ei[(size_t)E + e];
    if ((unsigned)r >= (unsigned)n || (unsigned)c >= (unsigned)n) return;
    int slot = atomicSub(&g_cnt[c], 1) - 1;   // absolute index in g_src
    g_src[slot] = r;
}

// ---------------------------------------------------------------------------
// K5: per-dst gather, 4 threads per node (feature split, 8B quarters).
// out = di * (sum_{s in seg} h_scaled[s] + h_scaled[i]) + b.
// ---------------------------------------------------------------------------
__global__ void __launch_bounds__(256)
k_out(const float* __restrict__ b, float4* __restrict__ out4, int n) {
    int tid  = threadIdx.x;
    int lane = tid & 3;
    int i    = blockIdx.x * 64 + (tid >> 2);
    if (i >= n) return;

    float4 bq = reinterpret_cast<const float4*>(b)[lane];

    int2 seg = __ldg(&g_seg[i]);
    float di = g_dinv[i];

    float4 acc = make_float4(0.f, 0.f, 0.f, 0.f);

    int j = seg.x;
    for (; j + 2 <= seg.y; j += 2) {
        int sA = __ldg(&g_src[j]);
        int sB = __ldg(&g_src[j + 1]);
        uint2 pA = __ldg(&reinterpret_cast<const uint2*>(g_hs + (size_t)sA * F)[lane]);
        uint2 pB = __ldg(&reinterpret_cast<const uint2*>(g_hs + (size_t)sB * F)[lane]);
        float2 a0 = __half22float2(*reinterpret_cast<const __half2*>(&pA.x));
        float2 a1 = __half22float2(*reinterpret_cast<const __half2*>(&pA.y));
        float2 b0 = __half22float2(*reinterpret_cast<const __half2*>(&pB.x));
        float2 b1 = __half22float2(*reinterpret_cast<const __half2*>(&pB.y));
        acc.x += a0.x + b0.x;
        acc.y += a0.y + b0.y;
        acc.z += a1.x + b1.x;
        acc.w += a1.y + b1.y;
    }
    if (j < seg.y) {
        int s = __ldg(&g_src[j]);
        uint2 p = __ldg(&reinterpret_cast<const uint2*>(g_hs + (size_t)s * F)[lane]);
        float2 f0 = __half22float2(*reinterpret_cast<const __half2*>(&p.x));
        float2 f1 = __half22float2(*reinterpret_cast<const __half2*>(&p.y));
        acc.x += f0.x;
        acc.y += f0.y;
        acc.z += f1.x;
        acc.w += f1.y;
    }

    uint2 pi = reinterpret_cast<const uint2*>(g_hs + (size_t)i * F)[lane];
    float2 v0 = __half22float2(*reinterpret_cast<const __half2*>(&pi.x));
    float2 v1 = __half22float2(*reinterpret_cast<const __half2*>(&pi.y));
    acc.x += v0.x;
    acc.y += v0.y;
    acc.z += v1.x;
    acc.w += v1.y;

    out4[(size_t)i * 4 + lane] = make_float4(
        fmaf(acc.x, di, bq.x),
        fmaf(acc.y, di, bq.y),
        fmaf(acc.z, di, bq.z),
        fmaf(acc.w, di, bq.w));
}

// ---------------------------------------------------------------------------
// launch
// ---------------------------------------------------------------------------
extern "C" void kernel_launch(void* const* d_in, const int* in_sizes, int n_in,
                              void* d_out, int out_size) {
    const float* x   = (const float*)d_in[0];
    const int*   ei  = (const int*)d_in[1];  // int32 (JAX x64 disabled)
    const float* W   = (const float*)d_in[2];
    const float* b   = (const float*)d_in[3];
    float*       out = (float*)d_out;

    int n = in_sizes[0] / F;   // 1,000,000
    int E = in_sizes[1] / 2;   // 4,000,000
    if (E > MAX_E) E = MAX_E;

    const int T = 256;
    int n4 = (n + 3) / 4;

    k_zero<<<(n4 + T - 1) / T, T>>>(n4);
    k_hist<<<(E + T - 1) / T, T>>>(ei + (size_t)E, E, n);
    k_scan<<<(n + SCAN_B - 1) / SCAN_B, SCAN_B>>>(n);
    k_h<<<(n + T - 1) / T, T>>>((const float4*)x, W, n);
    k_scatter<<<(E + T - 1) / T, T>>>(ei, E, n);
    k_out<<<(n * 4 + T - 1) / T, T>>>(b, (float4*)out, n);
}

// round 9
// speedup vs baseline: 1.4161x; 1.4161x over previous
#include <cuda_runtime.h>
#include <cuda_fp16.h>
#include <stdint.h>

#define N_NODES 1000000
#define F 16
#define MAX_E 4000000
#define SCAN_B 1024

// Scratch (allocation-free rule: __device__ globals)
__device__ __half g_h[(size_t)N_NODES * F];   // h = x @ W (fp16, 32MB)
__device__ float  g_dinv[N_NODES];            // rsqrt(deg + 1)
__device__ int    g_cnt[N_NODES];             // histogram -> downward cursors
__device__ int    g_off[N_NODES + 1];         // CSR offsets (exclusive scan)
__device__ int    g_bsum[(N_NODES + SCAN_B - 1) / SCAN_B];
__device__ int    g_src[MAX_E];               // src ids grouped by dst

// ---------------------------------------------------------------------------
// K1: histogram of dst (= degree without self loop). int4-vectorized reads.
// ---------------------------------------------------------------------------
__global__ void k_hist(const int4* __restrict__ col4, int E4, int E, int n) {
    int t = blockIdx.x * blockDim.x + threadIdx.x;
    if (t < E4) {
        int4 c4 = __ldg(&col4[t]);
        if ((unsigned)c4.x < (unsigned)n) atomicAdd(&g_cnt[c4.x], 1);
        if ((unsigned)c4.y < (unsigned)n) atomicAdd(&g_cnt[c4.y], 1);
        if ((unsigned)c4.z < (unsigned)n) atomicAdd(&g_cnt[c4.z], 1);
        if ((unsigned)c4.w < (unsigned)n) atomicAdd(&g_cnt[c4.w], 1);
    }
    // tail (E not multiple of 4)
    int tail = E & 3;
    if (t < tail) {
        const int* col = (const int*)col4;
        int c = col[E - 1 - t];
        if ((unsigned)c < (unsigned)n) atomicAdd(&g_cnt[c], 1);
    }
}

// ---------------------------------------------------------------------------
// K2a: per-block exclusive scan of g_cnt -> g_off, block totals -> g_bsum
// ---------------------------------------------------------------------------
__global__ void __launch_bounds__(SCAN_B)
k_scan_block(int n) {
    __shared__ int s[SCAN_B];
    int i = blockIdx.x * SCAN_B + threadIdx.x;
    int v = (i < n) ? g_cnt[i] : 0;
    s[threadIdx.x] = v;
    __syncthreads();
#pragma unroll
    for (int d = 1; d < SCAN_B; d <<= 1) {
        int t = (threadIdx.x >= d) ? s[threadIdx.x - d] : 0;
        __syncthreads();
        s[threadIdx.x] += t;
        __syncthreads();
    }
    if (i < n) g_off[i] = s[threadIdx.x] - v;   // exclusive
    if (threadIdx.x == SCAN_B - 1) g_bsum[blockIdx.x] = s[SCAN_B - 1];
}

// ---------------------------------------------------------------------------
// K2b: exclusive scan of block sums (single block; nb <= 1024)
// ---------------------------------------------------------------------------
__global__ void __launch_bounds__(SCAN_B)
k_scan_top(int nb) {
    __shared__ int s[SCAN_B];
    int v = (threadIdx.x < nb) ? g_bsum[threadIdx.x] : 0;
    s[threadIdx.x] = v;
    __syncthreads();
#pragma unroll
    for (int d = 1; d < SCAN_B; d <<= 1) {
        int t = (threadIdx.x >= d) ? s[threadIdx.x - d] : 0;
        __syncthreads();
        s[threadIdx.x] += t;
        __syncthreads();
    }
    if (threadIdx.x < nb) g_bsum[threadIdx.x] = s[threadIdx.x] - v;  // exclusive
}

// ---------------------------------------------------------------------------
// K2c: add block prefixes; dinv; cursor g_cnt[i] = segment END; off[n]=E
// ---------------------------------------------------------------------------
__global__ void k_finish(int n, int E) {
    int i = blockIdx.x * blockDim.x + threadIdx.x;
    if (i < n) {
        int base = g_off[i] + g_bsum[i / SCAN_B];
        int cnt  = g_cnt[i];
        g_off[i]  = base;
        g_cnt[i]  = base + cnt;           // downward cursor = segment end
        g_dinv[i] = rsqrtf((float)cnt + 1.0f);
    }
    if (i == 0) g_off[n] = E;
}

// ---------------------------------------------------------------------------
// K3: h = x @ W -> g_h (fp16). Pure streaming.
// ---------------------------------------------------------------------------
__global__ void __launch_bounds__(256)
k_h(const float4* __restrict__ x4, const float* __restrict__ W, int n) {
    __shared__ float sW[F * F];
    if (threadIdx.x < F * F) sW[threadIdx.x] = W[threadIdx.x];
    __syncthreads();

    int i = blockIdx.x * blockDim.x + threadIdx.x;
    if (i >= n) return;

    float4 xv0 = x4[(size_t)i * 4 + 0];
    float4 xv1 = x4[(size_t)i * 4 + 1];
    float4 xv2 = x4[(size_t)i * 4 + 2];
    float4 xv3 = x4[(size_t)i * 4 + 3];
    float xr[F] = {xv0.x, xv0.y, xv0.z, xv0.w,
                   xv1.x, xv1.y, xv1.z, xv1.w,
                   xv2.x, xv2.y, xv2.z, xv2.w,
                   xv3.x, xv3.y, xv3.z, xv3.w};

    float acc[F];
#pragma unroll
    for (int j = 0; j < F; j++) acc[j] = 0.0f;
#pragma unroll
    for (int k = 0; k < F; k++) {
        float xk = xr[k];
#pragma unroll
        for (int j = 0; j < F; j++) acc[j] = fmaf(xk, sW[k * F + j], acc[j]);
    }

    uint4 hpk[2];
    __half2* hh = reinterpret_cast<__half2*>(&hpk[0]);
#pragma unroll
    for (int q = 0; q < 8; q++)
        hh[q] = __floats2half2_rn(acc[2 * q], acc[2 * q + 1]);
    uint4* hp = reinterpret_cast<uint4*>(g_h + (size_t)i * F);
    hp[0] = hpk[0];
    hp[1] = hpk[1];
}

// ---------------------------------------------------------------------------
// K4: scatter src ids. Cursor decrement yields the ABSOLUTE slot directly
// (no g_off lookup -- saves a random 32B sector per edge).
// ---------------------------------------------------------------------------
__global__ void k_scatter(const int* __restrict__ ei, int E, int n) {
    int e = blockIdx.x * blockDim.x + threadIdx.x;
    if (e >= E) return;
    int r = ei[e];
    int c = ei[(size_t)E + e];
    if ((unsigned)r >= (unsigned)n || (unsigned)c >= (unsigned)n) return;
    int slot = atomicSub(&g_cnt[c], 1) - 1;   // absolute index in g_src
    g_src[slot] = r;
}

// ---------------------------------------------------------------------------
// K5: per-dst gather, 4 threads per node (feature split, 8B quarters).
// Group lane q owns features [4q,4q+4) = 4 halves = 8 bytes (uint2).
// ---------------------------------------------------------------------------
__global__ void __launch_bounds__(256)
k_out(const float* __restrict__ b, float4* __restrict__ out4, int n) {
    int tid  = threadIdx.x;
    int lane = tid & 3;
    int i    = blockIdx.x * 64 + (tid >> 2);
    if (i >= n) return;

    float4 bq = reinterpret_cast<const float4*>(b)[lane];

    int s0 = __ldg(&g_off[i]);
    int s1 = __ldg(&g_off[i + 1]);
    float di = g_dinv[i];

    float4 acc = make_float4(0.f, 0.f, 0.f, 0.f);

    int j = s0;
    for (; j + 2 <= s1; j += 2) {
        int sA = __ldg(&g_src[j]);
        int sB = __ldg(&g_src[j + 1]);
        float dA = __ldg(&g_dinv[sA]);
        float dB = __ldg(&g_dinv[sB]);
        uint2 pA = __ldg(&reinterpret_cast<const uint2*>(g_h + (size_t)sA * F)[lane]);
        uint2 pB = __ldg(&reinterpret_cast<const uint2*>(g_h + (size_t)sB * F)[lane]);
        float2 a0 = __half22float2(*reinterpret_cast<const __half2*>(&pA.x));
        float2 a1 = __half22float2(*reinterpret_cast<const __half2*>(&pA.y));
        float2 b0 = __half22float2(*reinterpret_cast<const __half2*>(&pB.x));
        float2 b1 = __half22float2(*reinterpret_cast<const __half2*>(&pB.y));
        acc.x = fmaf(a0.x, dA, fmaf(b0.x, dB, acc.x));
        acc.y = fmaf(a0.y, dA, fmaf(b0.y, dB, acc.y));
        acc.z = fmaf(a1.x, dA, fmaf(b1.x, dB, acc.z));
        acc.w = fmaf(a1.y, dA, fmaf(b1.y, dB, acc.w));
    }
    if (j < s1) {
        int s = __ldg(&g_src[j]);
        float ds = __ldg(&g_dinv[s]);
        uint2 p = __ldg(&reinterpret_cast<const uint2*>(g_h + (size_t)s * F)[lane]);
        float2 f0 = __half22float2(*reinterpret_cast<const __half2*>(&p.x));
        float2 f1 = __half22float2(*reinterpret_cast<const __half2*>(&p.y));
        acc.x = fmaf(f0.x, ds, acc.x);
        acc.y = fmaf(f0.y, ds, acc.y);
        acc.z = fmaf(f1.x, ds, acc.z);
        acc.w = fmaf(f1.y, ds, acc.w);
    }

    // self-loop quarter from fp16 h[i]
    uint2 pi = reinterpret_cast<const uint2*>(g_h + (size_t)i * F)[lane];
    float2 v0 = __half22float2(*reinterpret_cast<const __half2*>(&pi.x));
    float2 v1 = __half22float2(*reinterpret_cast<const __half2*>(&pi.y));

    float dii = di * di;
    out4[(size_t)i * 4 + lane] = make_float4(
        fmaf(acc.x, di, fmaf(v0.x, dii, bq.x)),
        fmaf(acc.y, di, fmaf(v0.y, dii, bq.y)),
        fmaf(acc.z, di, fmaf(v1.x, dii, bq.z)),
        fmaf(acc.w, di, fmaf(v1.y, dii, bq.w)));
}

// ---------------------------------------------------------------------------
// launch
// ---------------------------------------------------------------------------
extern "C" void kernel_launch(void* const* d_in, const int* in_sizes, int n_in,
                              void* d_out, int out_size) {
    const float* x   = (const float*)d_in[0];
    const int*   ei  = (const int*)d_in[1];  // int32 (JAX x64 disabled)
    const float* W   = (const float*)d_in[2];
    const float* b   = (const float*)d_in[3];
    float*       out = (float*)d_out;

    int n = in_sizes[0] / F;   // 1,000,000
    int E = in_sizes[1] / 2;   // 4,000,000
    if (E > MAX_E) E = MAX_E;

    const int T = 256;
    int nb = (n + SCAN_B - 1) / SCAN_B;
    int E4 = E / 4;

    // zero the histogram without a kernel launch (capture-legal async memset)
    void* cnt_ptr = nullptr;
    cudaGetSymbolAddress(&cnt_ptr, g_cnt);
    cudaMemsetAsync(cnt_ptr, 0, (size_t)n * sizeof(int));

    k_hist<<<(E4 + T - 1) / T, T>>>((const int4*)(ei + (size_t)E), E4, E, n);
    k_scan_block<<<nb, SCAN_B>>>(n);
    k_scan_top<<<1, SCAN_B>>>(nb);
    k_finish<<<(n + T - 1) / T, T>>>(n, E);
    k_h<<<(n + T - 1) / T, T>>>((const float4*)x, W, n);
    k_scatter<<<(E + T - 1) / T, T>>>(ei, E, n);
    k_out<<<(n * 4 + T - 1) / T, T>>>(b, (float4*)out, n);
}

// round 10
// speedup vs baseline: 1.4452x; 1.0206x over previous
#include <cuda_runtime.h>
#include <cuda_fp16.h>
#include <stdint.h>

#define N_NODES 1000000
#define F 16
#define MAX_E 4000000
#define SCAN_B 1024

// Scratch (allocation-free rule: __device__ globals)
__device__ __half g_hs[(size_t)N_NODES * F];  // (x@W)*dinv, fp16 (32MB)
__device__ float  g_dinv[N_NODES];            // rsqrt(deg + 1)
__device__ int    g_cnt[N_NODES];             // histogram -> downward cursors
__device__ int    g_off[N_NODES + 1];         // CSR offsets (exclusive scan)
__device__ int    g_bsum[(N_NODES + SCAN_B - 1) / SCAN_B];
__device__ int    g_src[MAX_E];               // src ids grouped by dst

// ---------------------------------------------------------------------------
// K1: histogram of dst (= degree without self loop). int4-vectorized reads.
// ---------------------------------------------------------------------------
__global__ void k_hist(const int4* __restrict__ col4, int E4, int E, int n) {
    int t = blockIdx.x * blockDim.x + threadIdx.x;
    if (t < E4) {
        int4 c4 = __ldg(&col4[t]);
        if ((unsigned)c4.x < (unsigned)n) atomicAdd(&g_cnt[c4.x], 1);
        if ((unsigned)c4.y < (unsigned)n) atomicAdd(&g_cnt[c4.y], 1);
        if ((unsigned)c4.z < (unsigned)n) atomicAdd(&g_cnt[c4.z], 1);
        if ((unsigned)c4.w < (unsigned)n) atomicAdd(&g_cnt[c4.w], 1);
    }
    // tail (E not multiple of 4)
    int tail = E & 3;
    if (t < tail) {
        const int* col = (const int*)col4;
        int c = col[E - 1 - t];
        if ((unsigned)c < (unsigned)n) atomicAdd(&g_cnt[c], 1);
    }
}

// ---------------------------------------------------------------------------
// K2a: per-block exclusive scan of g_cnt -> g_off, block totals -> g_bsum
// ---------------------------------------------------------------------------
__global__ void __launch_bounds__(SCAN_B)
k_scan_block(int n) {
    __shared__ int s[SCAN_B];
    int i = blockIdx.x * SCAN_B + threadIdx.x;
    int v = (i < n) ? g_cnt[i] : 0;
    s[threadIdx.x] = v;
    __syncthreads();
#pragma unroll
    for (int d = 1; d < SCAN_B; d <<= 1) {
        int t = (threadIdx.x >= d) ? s[threadIdx.x - d] : 0;
        __syncthreads();
        s[threadIdx.x] += t;
        __syncthreads();
    }
    if (i < n) g_off[i] = s[threadIdx.x] - v;   // exclusive
    if (threadIdx.x == SCAN_B - 1) g_bsum[blockIdx.x] = s[SCAN_B - 1];
}

// ---------------------------------------------------------------------------
// K2b: exclusive scan of block sums (single block; nb <= 1024)
// ---------------------------------------------------------------------------
__global__ void __launch_bounds__(SCAN_B)
k_scan_top(int nb) {
    __shared__ int s[SCAN_B];
    int v = (threadIdx.x < nb) ? g_bsum[threadIdx.x] : 0;
    s[threadIdx.x] = v;
    __syncthreads();
#pragma unroll
    for (int d = 1; d < SCAN_B; d <<= 1) {
        int t = (threadIdx.x >= d) ? s[threadIdx.x - d] : 0;
        __syncthreads();
        s[threadIdx.x] += t;
        __syncthreads();
    }
    if (threadIdx.x < nb) g_bsum[threadIdx.x] = s[threadIdx.x] - v;  // exclusive
}

// ---------------------------------------------------------------------------
// K2c: add block prefixes; dinv; cursor g_cnt[i] = segment END; off[n]=E
// ---------------------------------------------------------------------------
__global__ void k_finish(int n, int E) {
    int i = blockIdx.x * blockDim.x + threadIdx.x;
    if (i < n) {
        int base = g_off[i] + g_bsum[i / SCAN_B];
        int cnt  = g_cnt[i];
        g_off[i]  = base;
        g_cnt[i]  = base + cnt;           // downward cursor = segment end
        g_dinv[i] = rsqrtf((float)cnt + 1.0f);
    }
    if (i == 0) g_off[n] = E;
}

// ---------------------------------------------------------------------------
// K3: h_scaled = (x @ W) * dinv -> g_hs (fp16). Pure streaming.
// (runs after k_finish so g_dinv is ready; read is coalesced)
// ---------------------------------------------------------------------------
__global__ void __launch_bounds__(256)
k_h(const float4* __restrict__ x4, const float* __restrict__ W, int n) {
    __shared__ float sW[F * F];
    if (threadIdx.x < F * F) sW[threadIdx.x] = W[threadIdx.x];
    __syncthreads();

    int i = blockIdx.x * blockDim.x + threadIdx.x;
    if (i >= n) return;

    float4 xv0 = x4[(size_t)i * 4 + 0];
    float4 xv1 = x4[(size_t)i * 4 + 1];
    float4 xv2 = x4[(size_t)i * 4 + 2];
    float4 xv3 = x4[(size_t)i * 4 + 3];
    float xr[F] = {xv0.x, xv0.y, xv0.z, xv0.w,
                   xv1.x, xv1.y, xv1.z, xv1.w,
                   xv2.x, xv2.y, xv2.z, xv2.w,
                   xv3.x, xv3.y, xv3.z, xv3.w};

    float acc[F];
#pragma unroll
    for (int j = 0; j < F; j++) acc[j] = 0.0f;
#pragma unroll
    for (int k = 0; k < F; k++) {
        float xk = xr[k];
#pragma unroll
        for (int j = 0; j < F; j++) acc[j] = fmaf(xk, sW[k * F + j], acc[j]);
    }

    float di = g_dinv[i];

    uint4 hpk[2];
    __half2* hh = reinterpret_cast<__half2*>(&hpk[0]);
#pragma unroll
    for (int q = 0; q < 8; q++)
        hh[q] = __floats2half2_rn(acc[2 * q] * di, acc[2 * q + 1] * di);
    uint4* hp = reinterpret_cast<uint4*>(g_hs + (size_t)i * F);
    hp[0] = hpk[0];
    hp[1] = hpk[1];
}

// ---------------------------------------------------------------------------
// K4: scatter src ids. Cursor decrement yields the ABSOLUTE slot directly.
// ---------------------------------------------------------------------------
__global__ void k_scatter(const int* __restrict__ ei, int E, int n) {
    int e = blockIdx.x * blockDim.x + threadIdx.x;
    if (e >= E) return;
    int r = ei[e];
    int c = ei[(size_t)E + e];
    if ((unsigned)r >= (unsigned)n || (unsigned)c >= (unsigned)n) return;
    int slot = atomicSub(&g_cnt[c], 1) - 1;   // absolute index in g_src
    g_src[slot] = r;
}

// ---------------------------------------------------------------------------
// K5: per-dst gather, 4 threads per node (feature split, 8B quarters).
// out = di * (sum_{s in seg} hs[s] + hs[i]) + b.  No per-edge dinv gather.
// ---------------------------------------------------------------------------
__global__ void __launch_bounds__(256)
k_out(const float* __restrict__ b, float4* __restrict__ out4, int n) {
    int tid  = threadIdx.x;
    int lane = tid & 3;
    int i    = blockIdx.x * 64 + (tid >> 2);
    if (i >= n) return;

    float4 bq = reinterpret_cast<const float4*>(b)[lane];

    int s0 = __ldg(&g_off[i]);
    int s1 = __ldg(&g_off[i + 1]);
    float di = g_dinv[i];

    float4 acc = make_float4(0.f, 0.f, 0.f, 0.f);

    int j = s0;
    for (; j + 2 <= s1; j += 2) {
        int sA = __ldg(&g_src[j]);
        int sB = __ldg(&g_src[j + 1]);
        uint2 pA = __ldg(&reinterpret_cast<const uint2*>(g_hs + (size_t)sA * F)[lane]);
        uint2 pB = __ldg(&reinterpret_cast<const uint2*>(g_hs + (size_t)sB * F)[lane]);
        float2 a0 = __half22float2(*reinterpret_cast<const __half2*>(&pA.x));
        float2 a1 = __half22float2(*reinterpret_cast<const __half2*>(&pA.y));
        float2 b0 = __half22float2(*reinterpret_cast<const __half2*>(&pB.x));
        float2 b1 = __half22float2(*reinterpret_cast<const __half2*>(&pB.y));
        acc.x += a0.x + b0.x;
        acc.y += a0.y + b0.y;
        acc.z += a1.x + b1.x;
        acc.w += a1.y + b1.y;
    }
    if (j < s1) {
        int s = __ldg(&g_src[j]);
        uint2 p = __ldg(&reinterpret_cast<const uint2*>(g_hs + (size_t)s * F)[lane]);
        float2 f0 = __half22float2(*reinterpret_cast<const __half2*>(&p.x));
        float2 f1 = __half22float2(*reinterpret_cast<const __half2*>(&p.y));
        acc.x += f0.x;
        acc.y += f0.y;
        acc.z += f1.x;
        acc.w += f1.y;
    }

    // self-loop: hs[i] (already *di), then whole sum * di
    uint2 pi = reinterpret_cast<const uint2*>(g_hs + (size_t)i * F)[lane];
    float2 v0 = __half22float2(*reinterpret_cast<const __half2*>(&pi.x));
    float2 v1 = __half22float2(*reinterpret_cast<const __half2*>(&pi.y));
    acc.x += v0.x;
    acc.y += v0.y;
    acc.z += v1.x;
    acc.w += v1.y;

    out4[(size_t)i * 4 + lane] = make_float4(
        fmaf(acc.x, di, bq.x),
        fmaf(acc.y, di, bq.y),
        fmaf(acc.z, di, bq.z),
        fmaf(acc.w, di, bq.w));
}

// ---------------------------------------------------------------------------
// launch
// ---------------------------------------------------------------------------
extern "C" void kernel_launch(void* const* d_in, const int* in_sizes, int n_in,
                              void* d_out, int out_size) {
    const float* x   = (const float*)d_in[0];
    const int*   ei  = (const int*)d_in[1];  // int32 (JAX x64 disabled)
    const float* W   = (const float*)d_in[2];
    const float* b   = (const float*)d_in[3];
    float*       out = (float*)d_out;

    int n = in_sizes[0] / F;   // 1,000,000
    int E = in_sizes[1] / 2;   // 4,000,000
    if (E > MAX_E) E = MAX_E;

    const int T = 256;
    int nb = (n + SCAN_B - 1) / SCAN_B;
    int E4 = E / 4;

    // zero the histogram without a kernel launch (capture-legal async memset)
    void* cnt_ptr = nullptr;
    cudaGetSymbolAddress(&cnt_ptr, g_cnt);
    cudaMemsetAsync(cnt_ptr, 0, (size_t)n * sizeof(int));

    k_hist<<<(E4 + T - 1) / T, T>>>((const int4*)(ei + (size_t)E), E4, E, n);
    k_scan_block<<<nb, SCAN_B>>>(n);
    k_scan_top<<<1, SCAN_B>>>(nb);
    k_finish<<<(n + T - 1) / T, T>>>(n, E);
    k_h<<<(n + T - 1) / T, T>>>((const float4*)x, W, n);
    k_scatter<<<(E + T - 1) / T, T>>>(ei, E, n);
    k_out<<<(n * 4 + T - 1) / T, T>>>(b, (float4*)out, n);
}

// round 11
// speedup vs baseline: 1.4817x; 1.0253x over previous
#include <cuda_runtime.h>
#include <cuda_fp16.h>
#include <stdint.h>

#define N_NODES 1000000
#define F 16
#define MAX_E 4000000
#define SCAN_B 1024
#define NB_MAX ((N_NODES + SCAN_B - 1) / SCAN_B)

// Scratch (allocation-free rule: __device__ globals)
__device__ __half g_hs[(size_t)N_NODES * F];  // (x@W)*dinv, fp16 (32MB)
__device__ float  g_dinv[N_NODES];            // rsqrt(deg + 1)
__device__ int    g_cnt[N_NODES];             // histogram -> downward cursors
__device__ int    g_off[N_NODES + 1];         // CSR offsets
__device__ int    g_bsum[NB_MAX];             // per-scanblock totals
__device__ int    g_src[MAX_E];               // src ids grouped by dst

// ---------------------------------------------------------------------------
// K1: histogram of dst (= degree without self loop). int4-vectorized reads.
// ---------------------------------------------------------------------------
__global__ void k_hist(const int4* __restrict__ col4, int E4, int E, int n) {
    int t = blockIdx.x * blockDim.x + threadIdx.x;
    if (t < E4) {
        int4 c4 = __ldg(&col4[t]);
        if ((unsigned)c4.x < (unsigned)n) atomicAdd(&g_cnt[c4.x], 1);
        if ((unsigned)c4.y < (unsigned)n) atomicAdd(&g_cnt[c4.y], 1);
        if ((unsigned)c4.z < (unsigned)n) atomicAdd(&g_cnt[c4.z], 1);
        if ((unsigned)c4.w < (unsigned)n) atomicAdd(&g_cnt[c4.w], 1);
    }
    int tail = E & 3;
    if (t < tail) {
        const int* col = (const int*)col4;
        int c = col[E - 1 - t];
        if ((unsigned)c < (unsigned)n) atomicAdd(&g_cnt[c], 1);
    }
}

// ---------------------------------------------------------------------------
// K2: per-block exclusive scan of g_cnt -> g_off, block totals -> g_bsum
// ---------------------------------------------------------------------------
__global__ void __launch_bounds__(SCAN_B)
k_scan_block(int n) {
    __shared__ int s[SCAN_B];
    int i = blockIdx.x * SCAN_B + threadIdx.x;
    int v = (i < n) ? g_cnt[i] : 0;
    s[threadIdx.x] = v;
    __syncthreads();
#pragma unroll
    for (int d = 1; d < SCAN_B; d <<= 1) {
        int t = (threadIdx.x >= d) ? s[threadIdx.x - d] : 0;
        __syncthreads();
        s[threadIdx.x] += t;
        __syncthreads();
    }
    if (i < n) g_off[i] = s[threadIdx.x] - v;   // block-local exclusive
    if (threadIdx.x == SCAN_B - 1) g_bsum[blockIdx.x] = s[SCAN_B - 1];
}

// ---------------------------------------------------------------------------
// K3 (fused): per 256-node block:
//   1. cooperative prefix: S = sum(g_bsum[0 .. sb-1]), sb = node/1024
//      (256-aligned block lies in exactly ONE 1024-wide scan block)
//   2. finish: base = local_off + S; g_off[i]=base; cursor g_cnt[i]=base+cnt;
//      dinv = rsqrt(cnt+1)
//   3. h_scaled = (x @ W) * dinv -> g_hs (fp16)
// Replaces k_scan_top + k_finish + k_h (removes a whole-GPU-idle single-block
// kernel and two launch gaps).
// ---------------------------------------------------------------------------
__global__ void __launch_bounds__(256)
k_fused(const float4* __restrict__ x4, const float* __restrict__ W,
        int n, int E) {
    __shared__ float sW[F * F];
    __shared__ int sred[8];
    __shared__ int sbase;

    int tid = threadIdx.x;
    sW[tid] = W[tid];                       // blockDim == 256 == F*F

    // --- cooperative prefix of g_bsum over [0, sb) ---
    int sb = (int)((blockIdx.x * 256) >> 10);  // scan-block index (constant per block)
    int v = 0;
    for (int t = tid; t < sb; t += 256) v += __ldg(&g_bsum[t]);
    // warp reduce
#pragma unroll
    for (int d = 16; d; d >>= 1) v += __shfl_down_sync(0xffffffffu, v, d);
    if ((tid & 31) == 0) sred[tid >> 5] = v;
    __syncthreads();
    if (tid == 0) {
        int s = 0;
#pragma unroll
        for (int w = 0; w < 8; w++) s += sred[w];
        sbase = s;
    }
    __syncthreads();
    int S = sbase;

    int i = blockIdx.x * 256 + tid;
    if (i < n) {
        // --- finish ---
        int cnt  = g_cnt[i];
        int base = g_off[i] + S;
        g_off[i] = base;
        g_cnt[i] = base + cnt;              // downward cursor = segment end
        float di = rsqrtf((float)cnt + 1.0f);
        g_dinv[i] = di;

        // --- h_scaled ---
        float4 xv0 = x4[(size_t)i * 4 + 0];
        float4 xv1 = x4[(size_t)i * 4 + 1];
        float4 xv2 = x4[(size_t)i * 4 + 2];
        float4 xv3 = x4[(size_t)i * 4 + 3];
        float xr[F] = {xv0.x, xv0.y, xv0.z, xv0.w,
                       xv1.x, xv1.y, xv1.z, xv1.w,
                       xv2.x, xv2.y, xv2.z, xv2.w,
                       xv3.x, xv3.y, xv3.z, xv3.w};

        float acc[F];
#pragma unroll
        for (int j = 0; j < F; j++) acc[j] = 0.0f;
#pragma unroll
        for (int k = 0; k < F; k++) {
            float xk = xr[k];
#pragma unroll
            for (int j = 0; j < F; j++) acc[j] = fmaf(xk, sW[k * F + j], acc[j]);
        }

        uint4 hpk[2];
        __half2* hh = reinterpret_cast<__half2*>(&hpk[0]);
#pragma unroll
        for (int q = 0; q < 8; q++)
            hh[q] = __floats2half2_rn(acc[2 * q] * di, acc[2 * q + 1] * di);
        uint4* hp = reinterpret_cast<uint4*>(g_hs + (size_t)i * F);
        hp[0] = hpk[0];
        hp[1] = hpk[1];
    }
    if (i == 0) g_off[n] = E;               // sentinel
}

// ---------------------------------------------------------------------------
// K4: scatter src ids. Cursor decrement yields the ABSOLUTE slot directly.
// ---------------------------------------------------------------------------
__global__ void k_scatter(const int* __restrict__ ei, int E, int n) {
    int e = blockIdx.x * blockDim.x + threadIdx.x;
    if (e >= E) return;
    int r = ei[e];
    int c = ei[(size_t)E + e];
    if ((unsigned)r >= (unsigned)n || (unsigned)c >= (unsigned)n) return;
    int slot = atomicSub(&g_cnt[c], 1) - 1;   // absolute index in g_src
    g_src[slot] = r;
}

// ---------------------------------------------------------------------------
// K5: per-dst gather, 4 threads per node (feature split, 8B quarters).
// out = di * (sum_{s in seg} hs[s] + hs[i]) + b.
// ---------------------------------------------------------------------------
__global__ void __launch_bounds__(256)
k_out(const float* __restrict__ b, float4* __restrict__ out4, int n) {
    int tid  = threadIdx.x;
    int lane = tid & 3;
    int i    = blockIdx.x * 64 + (tid >> 2);
    if (i >= n) return;

    float4 bq = reinterpret_cast<const float4*>(b)[lane];

    int s0 = __ldg(&g_off[i]);
    int s1 = __ldg(&g_off[i + 1]);
    float di = g_dinv[i];

    float4 acc = make_float4(0.f, 0.f, 0.f, 0.f);

    int j = s0;
    for (; j + 2 <= s1; j += 2) {
        int sA = __ldg(&g_src[j]);
        int sB = __ldg(&g_src[j + 1]);
        uint2 pA = __ldg(&reinterpret_cast<const uint2*>(g_hs + (size_t)sA * F)[lane]);
        uint2 pB = __ldg(&reinterpret_cast<const uint2*>(g_hs + (size_t)sB * F)[lane]);
        float2 a0 = __half22float2(*reinterpret_cast<const __half2*>(&pA.x));
        float2 a1 = __half22float2(*reinterpret_cast<const __half2*>(&pA.y));
        float2 b0 = __half22float2(*reinterpret_cast<const __half2*>(&pB.x));
        float2 b1 = __half22float2(*reinterpret_cast<const __half2*>(&pB.y));
        acc.x += a0.x + b0.x;
        acc.y += a0.y + b0.y;
        acc.z += a1.x + b1.x;
        acc.w += a1.y + b1.y;
    }
    if (j < s1) {
        int s = __ldg(&g_src[j]);
        uint2 p = __ldg(&reinterpret_cast<const uint2*>(g_hs + (size_t)s * F)[lane]);
        float2 f0 = __half22float2(*reinterpret_cast<const __half2*>(&p.x));
        float2 f1 = __half22float2(*reinterpret_cast<const __half2*>(&p.y));
        acc.x += f0.x;
        acc.y += f0.y;
        acc.z += f1.x;
        acc.w += f1.y;
    }

    // self-loop: hs[i] (already *di), then whole sum * di
    uint2 pi = reinterpret_cast<const uint2*>(g_hs + (size_t)i * F)[lane];
    float2 v0 = __half22float2(*reinterpret_cast<const __half2*>(&pi.x));
    float2 v1 = __half22float2(*reinterpret_cast<const __half2*>(&pi.y));
    acc.x += v0.x;
    acc.y += v0.y;
    acc.z += v1.x;
    acc.w += v1.y;

    out4[(size_t)i * 4 + lane] = make_float4(
        fmaf(acc.x, di, bq.x),
        fmaf(acc.y, di, bq.y),
        fmaf(acc.z, di, bq.z),
        fmaf(acc.w, di, bq.w));
}

// ---------------------------------------------------------------------------
// launch
// ---------------------------------------------------------------------------
extern "C" void kernel_launch(void* const* d_in, const int* in_sizes, int n_in,
                              void* d_out, int out_size) {
    const float* x   = (const float*)d_in[0];
    const int*   ei  = (const int*)d_in[1];  // int32 (JAX x64 disabled)
    const float* W   = (const float*)d_in[2];
    const float* b   = (const float*)d_in[3];
    float*       out = (float*)d_out;

    int n = in_sizes[0] / F;   // 1,000,000
    int E = in_sizes[1] / 2;   // 4,000,000
    if (E > MAX_E) E = MAX_E;

    const int T = 256;
    int nb = (n + SCAN_B - 1) / SCAN_B;
    int E4 = E / 4;

    // zero the histogram without a kernel launch (capture-legal async memset)
    void* cnt_ptr = nullptr;
    cudaGetSymbolAddress(&cnt_ptr, g_cnt);
    cudaMemsetAsync(cnt_ptr, 0, (size_t)n * sizeof(int));

    k_hist<<<(E4 + T - 1) / T, T>>>((const int4*)(ei + (size_t)E), E4, E, n);
    k_scan_block<<<nb, SCAN_B>>>(n);
    k_fused<<<(n + T - 1) / T, T>>>((const float4*)x, W, n, E);
    k_scatter<<<(E + T - 1) / T, T>>>(ei, E, n);
    k_out<<<(n * 4 + T - 1) / T, T>>>(b, (float4*)out, n);
}